// round 6
// baseline (speedup 1.0000x reference)
#include <cuda_runtime.h>

#define B_LEN 32
#define T_IN  128
#define T_LEN 129
#define M_LEN 40
#define NPIX  (B_LEN*T_LEN*M_LEN)            // 165,120
typedef unsigned long long ull;

// spike lists: per pixel 64 bytes (half0 lane-ids at +0, half1 lane-ids at +32), cnt 2B
__device__ unsigned char g_cil1[NPIX * 64];
__device__ unsigned char g_cnt1[NPIX * 2];
__device__ unsigned char g_cil2[NPIX * 64];
__device__ unsigned char g_cnt2[NPIX * 2];
// weights: float idx = tap*4096 + ci*64 + lane*2 + half   (co = half*32+lane)
__device__ float4 g_wt2[(12 * 64 * 64) / 4];
__device__ float4 g_wt3[(12 * 64 * 64) / 4];
__device__ float4 g_wft[(12 * 40 * 64) / 4]; // [o][m][c]
__device__ float  g_cnt[B_LEN * M_LEN * 64]; // [b][m][c] spike counts (layer 3)

__device__ __forceinline__ float lif_tau_div(float num) {
    const float TAUF = 10.0f / 7.0f;
    return __fdiv_rn(num, TAUF);
}
__device__ __forceinline__ void add_f32x2(ull& acc, ull w) {
    asm("add.rn.f32x2 %0, %1, %2;" : "=l"(acc) : "l"(acc), "l"(w));
}

// ---------------- weight transposes ----------------
__global__ void k_transpose(const float* __restrict__ w2, const float* __restrict__ w3,
                            const float* __restrict__ wf) {
    int i = blockIdx.x * 256 + threadIdx.x;
    if (i < 2 * 49152) {
        int which = i >= 49152;
        int j = i - which * 49152;
        int ci  = j & 63;
        int tap = (j >> 6) % 12;
        int co  = j / 768;
        const float* w = which ? w3 : w2;
        float* wt = which ? (float*)g_wt3 : (float*)g_wt2;
        wt[tap * 4096 + ci * 64 + (co & 31) * 2 + (co >> 5)] = w[co * 768 + ci * 12 + tap];
    } else if (i < 2 * 49152 + 30720) {
        int j = i - 2 * 49152;
        int c = j & 63;
        int m = (j >> 6) % 40;
        int o = j / 2560;
        ((float*)g_wft)[j] = wf[o * 2560 + c * 40 + m];
    }
}

// ---------------- spike emit: ballot -> compact byte list ----------------
__device__ __forceinline__ void emit2(bool s0, bool s1, int lane, unsigned lml, int pix,
                                      unsigned char* __restrict__ cil,
                                      unsigned char* __restrict__ cnt) {
    unsigned b0 = __ballot_sync(0xffffffffu, s0);
    unsigned b1 = __ballot_sync(0xffffffffu, s1);
    if (s0) cil[(size_t)pix * 64 + __popc(b0 & lml)]      = (unsigned char)lane;
    if (s1) cil[(size_t)pix * 64 + 32 + __popc(b1 & lml)] = (unsigned char)lane;
    if (lane == 0)
        *(unsigned short*)(cnt + pix * 2) =
            (unsigned short)(__popc(b0) | (__popc(b1) << 8));
}

// ---------------- conv1 + LIF1 fused: warp per (b,m,half) chain ----------------
__global__ void __launch_bounds__(256) k_conv1_lif(const float* __restrict__ x,
                                                   const float* __restrict__ w1) {
    int w    = (blockIdx.x * 256 + threadIdx.x) >> 5;
    int lane = threadIdx.x & 31;
    unsigned lml = (1u << lane) - 1u;
    int b    = w / 80;
    int r    = w % 80;
    int m    = r >> 1;
    int half = r & 1;
    int co   = half * 32 + lane;

    float wr[12];
#pragma unroll
    for (int k = 0; k < 12; ++k) wr[k] = w1[co * 12 + k];

    const float* xb = x + (size_t)b * T_IN * M_LEN + m;
    bool c0 = (m - 1 >= 0);
    bool c2 = (m + 1 < M_LEN);

    float win[4][3];
#pragma unroll
    for (int i = 0; i < 4; ++i)
#pragma unroll
        for (int j = 0; j < 3; ++j) win[i][j] = 0.0f;
#pragma unroll
    for (int i = 2; i < 4; ++i) {
        int ti = i - 2;
        win[i][0] = c0 ? xb[ti * M_LEN - 1] : 0.0f;
        win[i][1] = xb[ti * M_LEN];
        win[i][2] = c2 ? xb[ti * M_LEN + 1] : 0.0f;
    }

    float v = 0.0f;
    for (int t = 0; t < T_LEN; ++t) {
        float acc = 0.0f;
#pragma unroll
        for (int kh = 0; kh < 4; ++kh)
#pragma unroll
            for (int kw = 0; kw < 3; ++kw)
                acc = fmaf(wr[kh * 3 + kw], win[kh][kw], acc);

        v = v + lif_tau_div(acc - v);
        bool sp = (v >= 1.0f);
        if (sp) v = 0.0f;
        {   // emit into list1 (per-half)
            unsigned bal = __ballot_sync(0xffffffffu, sp);
            int pix = (b * T_LEN + t) * M_LEN + m;
            if (sp)
                g_cil1[(size_t)pix * 64 + half * 32 + __popc(bal & lml)] = (unsigned char)lane;
            if (lane == 0)
                g_cnt1[pix * 2 + half] = (unsigned char)__popc(bal);
        }

#pragma unroll
        for (int i = 0; i < 3; ++i)
#pragma unroll
            for (int j = 0; j < 3; ++j) win[i][j] = win[i + 1][j];
        int ti = t + 2;
        bool rv = (ti < T_IN);
        win[3][0] = (rv && c0) ? xb[ti * M_LEN - 1] : 0.0f;
        win[3][1] = rv ? xb[ti * M_LEN] : 0.0f;
        win[3][2] = (rv && c2) ? xb[ti * M_LEN + 1] : 0.0f;
    }
}

// ---------------- conv2 + LIF2 fused: systolic register ring ----------------
// warp per (b,m) chain; lane holds co pair {lane, lane+32} packed f32x2.
// ring of 13 pending outputs; row ti updates d = 4*kh; retires t = ti-6.
__global__ void __launch_bounds__(288, 1) k_sconv2_lif(const unsigned char* __restrict__ cil,
                                                       const unsigned char* __restrict__ cntb,
                                                       unsigned char* __restrict__ cil_o,
                                                       unsigned char* __restrict__ cnt_o) {
    const int PADT = 6, PADM = 3, DILM = 3;
    const int RS = 2 * PADT + 1;                 // 13
    extern __shared__ ull wsu[];                 // 24576 ull = 192KB weight table
    {
        float4* d4 = (float4*)wsu;
        for (int i = threadIdx.x; i < 12288; i += 288) d4[i] = g_wt2[i];
    }
    __syncthreads();

    int gw = blockIdx.x * 9 + (threadIdx.x >> 5);
    if (gw >= B_LEN * M_LEN) return;
    int lane = threadIdx.x & 31;
    unsigned lml = (1u << lane) - 1u;
    int b = gw / M_LEN;
    int m = gw % M_LEN;

    // kw validity (warp-constant)
    bool kwok[3];
    int  kwoff[3];
#pragma unroll
    for (int kw = 0; kw < 3; ++kw) {
        int mi = m - PADM + DILM * kw;
        kwok[kw]  = ((unsigned)mi < (unsigned)M_LEN);
        kwoff[kw] = mi;
    }

    ull acc[RS];
#pragma unroll
    for (int d = 0; d < RS; ++d) acc[d] = 0ull;
    float v0 = 0.0f, v1 = 0.0f;

    for (int ti = 0; ti < T_LEN + PADT; ++ti) {
        if (ti < T_LEN) {
            int rowbase = (b * T_LEN + ti) * M_LEN;
#pragma unroll
            for (int kw = 0; kw < 3; ++kw) {
                if (!kwok[kw]) continue;
                int inpix = rowbase + kwoff[kw];
                unsigned cc = *(const unsigned short*)(cntb + inpix * 2);
                if (!cc) continue;
                int n0 = cc & 255;
                int n1 = cc >> 8;
                const unsigned* lp = (const unsigned*)(cil + (size_t)inpix * 64);
                // half0: ci = byte (0..31)
                for (int j = 0; j < n0; j += 4) {
                    unsigned q = lp[j >> 2];
#pragma unroll
                    for (int k = 0; k < 4; ++k) {
                        if (j + k < n0) {
                            int ci = __byte_perm(q, 0, 0x4440 + k);
                            int wi = kw * 2048 + ci * 32 + lane;
#pragma unroll
                            for (int kh = 0; kh < 4; ++kh)
                                add_f32x2(acc[4 * kh], wsu[wi + kh * 6144]);
                        }
                    }
                }
                // half1: ci = 32 + byte
                for (int j = 0; j < n1; j += 4) {
                    unsigned q = lp[8 + (j >> 2)];
#pragma unroll
                    for (int k = 0; k < 4; ++k) {
                        if (j + k < n1) {
                            int ci = 32 + __byte_perm(q, 0, 0x4440 + k);
                            int wi = kw * 2048 + ci * 32 + lane;
#pragma unroll
                            for (int kh = 0; kh < 4; ++kh)
                                add_f32x2(acc[4 * kh], wsu[wi + kh * 6144]);
                        }
                    }
                }
            }
        }
        // retire t = ti - PADT from slot RS-1
        int t = ti - PADT;
        if (t >= 0) {
            union { ull u; float2 f; } r;
            r.u = acc[RS - 1];
            v0 = v0 + lif_tau_div(r.f.x - v0);
            v1 = v1 + lif_tau_div(r.f.y - v1);
            bool s0 = (v0 >= 1.0f);
            bool s1 = (v1 >= 1.0f);
            if (s0) v0 = 0.0f;
            if (s1) v1 = 0.0f;
            emit2(s0, s1, lane, lml, (b * T_LEN + t) * M_LEN + m, cil_o, cnt_o);
        }
        // shift ring
#pragma unroll
        for (int d = RS - 1; d >= 1; --d) acc[d] = acc[d - 1];
        acc[0] = 0ull;
    }
}

// ---------------- conv3 + LIF3 fused: systolic smem ring (49 slots) ----------------
// warp per (b,m); density near zero so weights via L1-cached LDG; retire -> counts.
__global__ void __launch_bounds__(288, 1) k_sconv3_lif(const unsigned char* __restrict__ cil,
                                                       const unsigned char* __restrict__ cntb) {
    const int PADT = 24, PADM = 9, DILM = 9, DILT = 16;
    const int RS = 2 * PADT + 1;                 // 49
    extern __shared__ ull ring[];                // 9 warps * 49 slots * 32 lanes
    int g    = threadIdx.x >> 5;
    int lane = threadIdx.x & 31;
    ull* rg = ring + (size_t)g * RS * 32 + lane;
    for (int s = 0; s < RS; ++s) rg[s * 32] = 0ull;
    __syncwarp();

    int gw = blockIdx.x * 9 + g;
    if (gw >= B_LEN * M_LEN) return;
    int b = gw / M_LEN;
    int m = gw % M_LEN;

    bool kwok[3];
    int  kwoff[3];
#pragma unroll
    for (int kw = 0; kw < 3; ++kw) {
        int mi = m - PADM + DILM * kw;
        kwok[kw]  = ((unsigned)mi < (unsigned)M_LEN);
        kwoff[kw] = mi;
    }

    const ull* wt = (const ull*)g_wt3;
    float v0 = 0.0f, v1 = 0.0f, c0 = 0.0f, c1 = 0.0f;
    int head = 0;   // slot holding d=0

    for (int ti = 0; ti < T_LEN + PADT; ++ti) {
        if (ti < T_LEN) {
            int rowbase = (b * T_LEN + ti) * M_LEN;
#pragma unroll
            for (int kw = 0; kw < 3; ++kw) {
                if (!kwok[kw]) continue;
                int inpix = rowbase + kwoff[kw];
                unsigned cc = *(const unsigned short*)(cntb + inpix * 2);
                if (!cc) continue;
                int n0 = cc & 255;
                int n1 = cc >> 8;
                const unsigned* lp = (const unsigned*)(cil + (size_t)inpix * 64);
                int slot[4];
#pragma unroll
                for (int kh = 0; kh < 4; ++kh) {
                    int s = head + DILT * kh;
                    if (s >= RS) s -= RS;
                    slot[kh] = s * 32;
                }
                for (int h = 0; h < 2; ++h) {
                    int n = h ? n1 : n0;
                    for (int j = 0; j < n; ++j) {
                        int ci = h * 32 + (int)cil[(size_t)inpix * 64 + h * 32 + j];
                        int wi = kw * 2048 + ci * 32 + lane;
#pragma unroll
                        for (int kh = 0; kh < 4; ++kh) {
                            ull a = rg[slot[kh]];
                            add_f32x2(a, __ldg(&wt[wi + kh * 6144]));
                            rg[slot[kh]] = a;
                        }
                    }
                }
                (void)lp;
            }
        }
        // retire t = ti - PADT (slot d = RS-1)
        int rs = head + RS - 1;
        if (rs >= RS) rs -= RS;
        int t = ti - PADT;
        if (t >= 0) {
            union { ull u; float2 f; } r;
            r.u = rg[rs * 32];
            v0 = v0 + lif_tau_div(r.f.x - v0);
            v1 = v1 + lif_tau_div(r.f.y - v1);
            bool s0 = (v0 >= 1.0f);
            bool s1 = (v1 >= 1.0f);
            if (s0) v0 = 0.0f;
            if (s1) v1 = 0.0f;
            c0 += s0 ? 1.0f : 0.0f;
            c1 += s1 ? 1.0f : 0.0f;
        }
        rg[rs * 32] = 0ull;
        head = rs;   // freed slot becomes next row's d=0
    }
    g_cnt[b * 2560 + m * 64 + lane]      = c0;
    g_cnt[b * 2560 + m * 64 + lane + 32] = c1;
}

// ---------------- FC + mean ----------------
__global__ void k_fc(const float* __restrict__ bf, float* __restrict__ out) {
    int o = blockIdx.x;
    int b = blockIdx.y;
    int tid = threadIdx.x;   // 128
    const float* wft = (const float*)g_wft;
    float p = 0.0f;
    for (int i = tid; i < 2560; i += 128)
        p = fmaf(g_cnt[b * 2560 + i], wft[o * 2560 + i], p);
#pragma unroll
    for (int off = 16; off; off >>= 1) p += __shfl_down_sync(0xffffffffu, p, off);
    __shared__ float wsum[4];
    if ((tid & 31) == 0) wsum[tid >> 5] = p;
    __syncthreads();
    if (tid == 0) {
        float tt = wsum[0] + wsum[1] + wsum[2] + wsum[3];
        out[b * 12 + o] = bf[o] + tt / 129.0f;
    }
}

#define SC2_SMEM (12 * 64 * 64 * 4)          // 196608
#define SC3_SMEM (9 * 49 * 32 * 8)           // 112896

extern "C" void kernel_launch(void* const* d_in, const int* in_sizes, int n_in,
                              void* d_out, int out_size) {
    const float* x  = (const float*)d_in[0];
    const float* w1 = (const float*)d_in[1];
    const float* w2 = (const float*)d_in[2];
    const float* w3 = (const float*)d_in[3];
    const float* wf = (const float*)d_in[4];
    const float* bf = (const float*)d_in[5];
    float* out = (float*)d_out;

    cudaFuncSetAttribute(k_sconv2_lif, cudaFuncAttributeMaxDynamicSharedMemorySize, SC2_SMEM);
    cudaFuncSetAttribute(k_sconv3_lif, cudaFuncAttributeMaxDynamicSharedMemorySize, SC3_SMEM);

    unsigned char* c1 = nullptr; cudaGetSymbolAddress((void**)&c1, g_cil1);
    unsigned char* n1 = nullptr; cudaGetSymbolAddress((void**)&n1, g_cnt1);
    unsigned char* c2 = nullptr; cudaGetSymbolAddress((void**)&c2, g_cil2);
    unsigned char* n2 = nullptr; cudaGetSymbolAddress((void**)&n2, g_cnt2);

    k_transpose<<<504, 256>>>(w2, w3, wf);

    // layer 1: conv1 + LIF1 -> list1
    k_conv1_lif<<<320, 256>>>(x, w1);

    // layer 2: conv2 + LIF2 fused (register ring) -> list2
    k_sconv2_lif<<<143, 288, SC2_SMEM>>>(c1, n1, c2, n2);

    // layer 3: conv3 + LIF3 fused (smem ring) -> counts
    k_sconv3_lif<<<143, 288, SC3_SMEM>>>(c2, n2);

    // FC head
    k_fc<<<dim3(12, 32), 128>>>(bf, out);
}

// round 7
// speedup vs baseline: 1.2697x; 1.2697x over previous
#include <cuda_runtime.h>

#define B_LEN 32
#define T_IN  128
#define T_LEN 129
#define M_LEN 40
#define NPIX  (B_LEN*T_LEN*M_LEN)            // 165,120
#define NTOT  (NPIX*64)
typedef unsigned long long ull;

// acts: [(b*40+m)*2+half][t][lane]
__device__ float  g_acts[NTOT];
__device__ unsigned char g_cil1[NPIX * 64];
__device__ unsigned char g_cnt1[NPIX * 2];
__device__ unsigned char g_cil2[NPIX * 64];
__device__ unsigned char g_cnt2[NPIX * 2];
// conv2 paired layout: float f = kw*16384 + ci*256 + pair*128 + lane*4 + j
//   kh = pair*2 + (j>>1), co = (j&1)*32 + lane
__device__ float4 g_wq2[49152 / 4];
// conv3 layout: float idx = tap*4096 + ci*64 + lane*2 + half
__device__ float4 g_wt3[49152 / 4];
__device__ float4 g_wft[30720 / 4];          // [o][m][c]
__device__ float  g_cnt[B_LEN * M_LEN * 64]; // [b][m][c]

__device__ __forceinline__ float lif_tau_div(float num) {
    const float TAUF = 10.0f / 7.0f;
    return __fdiv_rn(num, TAUF);
}
__device__ __forceinline__ void add_f32x2(ull& acc, ull w) {
    asm("add.rn.f32x2 %0, %1, %2;" : "=l"(acc) : "l"(acc), "l"(w));
}

// ---------------- weight transposes ----------------
__global__ void k_transpose(const float* __restrict__ w2, const float* __restrict__ w3,
                            const float* __restrict__ wf) {
    int i = blockIdx.x * 256 + threadIdx.x;
    if (i < 49152) {
        // g_wq2 paired layout
        int j    = i & 3;
        int lane = (i >> 2) & 31;
        int pair = (i >> 7) & 1;
        int ci   = (i >> 8) & 63;
        int kw   = i >> 14;
        int kh   = pair * 2 + (j >> 1);
        int co   = (j & 1) * 32 + lane;
        ((float*)g_wq2)[i] = w2[co * 768 + ci * 12 + kh * 3 + kw];
    } else if (i < 2 * 49152) {
        int j   = i - 49152;
        int ci  = j & 63;
        int tap = (j >> 6) % 12;
        int co  = j / 768;
        ((float*)g_wt3)[tap * 4096 + ci * 64 + (co & 31) * 2 + (co >> 5)] =
            w3[co * 768 + ci * 12 + tap];
    } else if (i < 2 * 49152 + 30720) {
        int j = i - 2 * 49152;
        int c = j & 63;
        int m = (j >> 6) % 40;
        int o = j / 2560;
        ((float*)g_wft)[j] = wf[o * 2560 + c * 40 + m];
    }
}

// ---------------- conv1 + LIF1 fused: warp per (b,m,half) chain ----------------
__global__ void __launch_bounds__(256) k_conv1_lif(const float* __restrict__ x,
                                                   const float* __restrict__ w1) {
    int w    = (blockIdx.x * 256 + threadIdx.x) >> 5;
    int lane = threadIdx.x & 31;
    unsigned lml = (1u << lane) - 1u;
    int b    = w / 80;
    int r    = w % 80;
    int m    = r >> 1;
    int half = r & 1;
    int co   = half * 32 + lane;

    float wr[12];
#pragma unroll
    for (int k = 0; k < 12; ++k) wr[k] = w1[co * 12 + k];

    const float* xb = x + (size_t)b * T_IN * M_LEN + m;
    bool c0 = (m - 1 >= 0);
    bool c2 = (m + 1 < M_LEN);

    float win[4][3];
#pragma unroll
    for (int i = 0; i < 4; ++i)
#pragma unroll
        for (int j = 0; j < 3; ++j) win[i][j] = 0.0f;
#pragma unroll
    for (int i = 2; i < 4; ++i) {
        int ti = i - 2;
        win[i][0] = c0 ? xb[ti * M_LEN - 1] : 0.0f;
        win[i][1] = xb[ti * M_LEN];
        win[i][2] = c2 ? xb[ti * M_LEN + 1] : 0.0f;
    }

    float v = 0.0f;
    for (int t = 0; t < T_LEN; ++t) {
        float acc = 0.0f;
#pragma unroll
        for (int kh = 0; kh < 4; ++kh)
#pragma unroll
            for (int kw = 0; kw < 3; ++kw)
                acc = fmaf(wr[kh * 3 + kw], win[kh][kw], acc);

        v = v + lif_tau_div(acc - v);
        bool sp = (v >= 1.0f);
        if (sp) v = 0.0f;
        {
            unsigned bal = __ballot_sync(0xffffffffu, sp);
            int pix = (b * T_LEN + t) * M_LEN + m;
            if (sp)
                g_cil1[(size_t)pix * 64 + half * 32 + __popc(bal & lml)] = (unsigned char)lane;
            if (lane == 0)
                g_cnt1[pix * 2 + half] = (unsigned char)__popc(bal);
        }

#pragma unroll
        for (int i = 0; i < 3; ++i)
#pragma unroll
            for (int j = 0; j < 3; ++j) win[i][j] = win[i + 1][j];
        int ti = t + 2;
        bool rv = (ti < T_IN);
        win[3][0] = (rv && c0) ? xb[ti * M_LEN - 1] : 0.0f;
        win[3][1] = rv ? xb[ti * M_LEN] : 0.0f;
        win[3][2] = (rv && c2) ? xb[ti * M_LEN + 1] : 0.0f;
    }
}

// ---------------- conv2: t-segmented systolic register ring ----------------
template<bool P0, bool P1>
__device__ __forceinline__ void row_list(const char* wkw, const unsigned* lp, int n,
                                         int woff, ull (&acc)[13], int lane) {
    for (int j = 0; j < n; j += 4) {
        unsigned q = lp[(woff + j) >> 2];
#pragma unroll
        for (int k = 0; k < 4; ++k) {
            if (j + k < n) {
                int ci = __byte_perm(q, 0, 0x4440 + k);
                const char* a = wkw + ci * 1024 + lane * 16;
                if (P0) {
                    ulonglong2 v = *(const ulonglong2*)a;          // kh0, kh1
                    add_f32x2(acc[0], v.x);
                    add_f32x2(acc[4], v.y);
                }
                if (P1) {
                    ulonglong2 v = *(const ulonglong2*)(a + 512);  // kh2, kh3
                    add_f32x2(acc[8], v.x);
                    add_f32x2(acc[12], v.y);
                }
            }
        }
    }
}

template<bool P0, bool P1>
__device__ __forceinline__ void proc_row(const char* wsm, const unsigned char* __restrict__ cil,
                                         int rowbase, const bool* kwok, const int* kwoff,
                                         const unsigned* cc, ull (&acc)[13], int lane) {
#pragma unroll
    for (int kw = 0; kw < 3; ++kw) {
        if (!kwok[kw]) continue;
        unsigned c = cc[kw];
        if (!c) continue;
        int n0 = c & 255;
        int n1 = c >> 8;
        int inpix = rowbase + kwoff[kw];
        const unsigned* lp = (const unsigned*)(cil + (size_t)inpix * 64);
        const char* wkw = wsm + kw * 65536;
        row_list<P0, P1>(wkw, lp, n0, 0, acc, lane);                 // half0 (ci 0..31)
        row_list<P0, P1>(wkw + 32768, lp, n1, 32, acc, lane);        // half1 (ci 32..63)
    }
}

__global__ void __launch_bounds__(832, 1) k_sconv2(const unsigned char* __restrict__ cil,
                                                   const unsigned char* __restrict__ cntb,
                                                   float* __restrict__ acts) {
    extern __shared__ char wsm[];
    {
        float4* d = (float4*)wsm;
        for (int i = threadIdx.x; i < 12288; i += 832) d[i] = g_wq2[i];
    }
    __syncthreads();

    int item = blockIdx.x * 26 + (threadIdx.x >> 5);
    if (item >= 3840) return;
    int lane  = threadIdx.x & 31;
    int chain = item % 1280;
    int seg   = item / 1280;
    int b = chain / 40;
    int m = chain % 40;
    int t0 = seg * 43;
    int t1 = t0 + 43;

    bool kwok[3];
    int  kwoff[3];
#pragma unroll
    for (int kw = 0; kw < 3; ++kw) {
        int mi = m - 3 + 3 * kw;
        kwok[kw]  = ((unsigned)mi < (unsigned)M_LEN);
        kwoff[kw] = mi;
    }

    ull acc[13];
#pragma unroll
    for (int d = 0; d < 13; ++d) acc[d] = 0ull;

    unsigned ccur[3];
    {
        int ti = t0 - 6;
#pragma unroll
        for (int kw = 0; kw < 3; ++kw)
            ccur[kw] = ((unsigned)ti < 129u && kwok[kw])
                ? *(const unsigned short*)(cntb + ((b * 129 + ti) * 40 + kwoff[kw]) * 2) : 0u;
    }

    for (int ti = t0 - 6; ti <= t1 + 5; ++ti) {
        unsigned cnxt[3];
        {
            int tn = ti + 1;
#pragma unroll
            for (int kw = 0; kw < 3; ++kw)
                cnxt[kw] = ((unsigned)tn < 129u && kwok[kw])
                    ? *(const unsigned short*)(cntb + ((b * 129 + tn) * 40 + kwoff[kw]) * 2) : 0u;
        }
        if ((unsigned)ti < 129u) {
            int rowbase = (b * 129 + ti) * 40;
            bool u0 = (ti + 6 >= t0) & (ti + 6 < t1);
            bool u1 = (ti + 2 >= t0) & (ti + 2 < t1);
            bool u2 = (ti - 2 >= t0) & (ti - 2 < t1);
            bool u3 = (ti - 6 >= t0) & (ti - 6 < t1);
            bool p0 = u0 | u1;
            bool p1 = u2 | u3;
            if (p0 & p1)
                proc_row<true, true>(wsm, cil, rowbase, kwok, kwoff, ccur, acc, lane);
            else if (p0)
                proc_row<true, false>(wsm, cil, rowbase, kwok, kwoff, ccur, acc, lane);
            else if (p1)
                proc_row<false, true>(wsm, cil, rowbase, kwok, kwoff, ccur, acc, lane);
        }
        int t = ti - 6;
        if (t >= t0 && t < t1) {
            union { ull u; float2 f; } r;
            r.u = acc[12];
            size_t row = ((size_t)(b * 40 + m) * 2) * 129 + t;
            acts[row * 32 + lane]         = r.f.x;
            acts[(row + 129) * 32 + lane] = r.f.y;
        }
#pragma unroll
        for (int d = 12; d >= 1; --d) acc[d] = acc[d - 1];
        acc[0] = 0ull;
        ccur[0] = cnxt[0]; ccur[1] = cnxt[1]; ccur[2] = cnxt[2];
    }
}

// ---------------- LIF scan: warp per (b,m,half) ----------------
template<int MODE>
__global__ void __launch_bounds__(256) k_lif_scan(const float* __restrict__ acts,
                                                  unsigned char* __restrict__ cil,
                                                  unsigned char* __restrict__ cntb) {
    int w    = (blockIdx.x * 256 + threadIdx.x) >> 5;
    int lane = threadIdx.x & 31;
    unsigned lml = (1u << lane) - 1u;
    int b    = w / 80;
    int r    = w % 80;
    int m    = r >> 1;
    int half = r & 1;
    const float* p = acts + ((size_t)((b * M_LEN + m) * 2 + half) * T_LEN) * 32 + lane;

    float v = 0.0f, scnt = 0.0f;
    float buf[8];
#pragma unroll
    for (int i = 0; i < 8; ++i) buf[i] = p[i * 32];

    for (int t8 = 0; t8 < 128; t8 += 8) {
#pragma unroll
        for (int k = 0; k < 8; ++k) {
            int t = t8 + k;
            float a = buf[k];
            int tn = t + 8;
            if (tn < T_LEN) buf[k] = p[tn * 32];
            v = v + lif_tau_div(a - v);
            bool sp = (v >= 1.0f);
            if (sp) v = 0.0f;
            if (MODE == 0) {
                unsigned bal = __ballot_sync(0xffffffffu, sp);
                int pix = (b * T_LEN + t) * M_LEN + m;
                if (sp) cil[(size_t)pix * 64 + half * 32 + __popc(bal & lml)] = (unsigned char)lane;
                if (lane == 0) cntb[pix * 2 + half] = (unsigned char)__popc(bal);
            } else {
                scnt += sp ? 1.0f : 0.0f;
            }
        }
    }
    {
        float a = buf[0];
        v = v + lif_tau_div(a - v);
        bool sp = (v >= 1.0f);
        if (sp) v = 0.0f;
        if (MODE == 0) {
            unsigned bal = __ballot_sync(0xffffffffu, sp);
            int pix = (b * T_LEN + 128) * M_LEN + m;
            if (sp) cil[(size_t)pix * 64 + half * 32 + __popc(bal & lml)] = (unsigned char)lane;
            if (lane == 0) cntb[pix * 2 + half] = (unsigned char)__popc(bal);
        } else {
            scnt += sp ? 1.0f : 0.0f;
        }
    }
    if (MODE == 1)
        g_cnt[b * 2560 + m * 64 + half * 32 + lane] = scnt;
}

// ---------------- conv3: warp-per-pixel gather, MLP count prefetch ----------------
__global__ void __launch_bounds__(1024) k_sconv3(const unsigned char* __restrict__ cil,
                                                 const unsigned char* __restrict__ cntb,
                                                 float* __restrict__ acts) {
    const ull* wt = (const ull*)g_wt3;
    int lane = threadIdx.x & 31;
    int wid  = (blockIdx.x * 1024 + threadIdx.x) >> 5;
    int nw   = gridDim.x * 32;

    for (int pix = wid; pix < NPIX; pix += nw) {
        int b = pix / (T_LEN * M_LEN);
        int r = pix % (T_LEN * M_LEN);
        int t = r / M_LEN;
        int m = r % M_LEN;

        unsigned cc[12];
        unsigned any = 0;
#pragma unroll
        for (int kh = 0; kh < 4; ++kh)
#pragma unroll
            for (int kw = 0; kw < 3; ++kw) {
                int ti = t - 24 + 16 * kh;
                int mi = m - 9 + 9 * kw;
                unsigned c = 0;
                if ((unsigned)ti < 129u && (unsigned)mi < 40u)
                    c = *(const unsigned short*)(cntb + ((b * 129 + ti) * 40 + mi) * 2);
                cc[kh * 3 + kw] = c;
                any |= c;
            }

        ull acc = 0ull;
        if (any) {
#pragma unroll
            for (int kh = 0; kh < 4; ++kh)
#pragma unroll
                for (int kw = 0; kw < 3; ++kw) {
                    unsigned c = cc[kh * 3 + kw];
                    if (!c) continue;
                    int ti = t - 24 + 16 * kh;
                    int mi = m - 9 + 9 * kw;
                    int inpix = (b * 129 + ti) * 40 + mi;
                    const unsigned char* l8 = cil + (size_t)inpix * 64;
                    int n0 = c & 255;
                    int n1 = c >> 8;
                    const ull* wtap = wt + (kh * 3 + kw) * 2048 + lane;
                    for (int j = 0; j < n0; ++j)
                        add_f32x2(acc, __ldg(wtap + (int)l8[j] * 32));
                    for (int j = 0; j < n1; ++j)
                        add_f32x2(acc, __ldg(wtap + (32 + (int)l8[32 + j]) * 32));
                }
        }
        union { ull u; float2 f; } cv;
        cv.u = acc;
        size_t row = ((size_t)(b * 40 + m) * 2) * 129 + t;
        acts[row * 32 + lane]         = cv.f.x;
        acts[(row + 129) * 32 + lane] = cv.f.y;
    }
}

// ---------------- FC + mean ----------------
__global__ void k_fc(const float* __restrict__ bf, float* __restrict__ out) {
    int o = blockIdx.x;
    int b = blockIdx.y;
    int tid = threadIdx.x;   // 128
    const float* wft = (const float*)g_wft;
    float p = 0.0f;
    for (int i = tid; i < 2560; i += 128)
        p = fmaf(g_cnt[b * 2560 + i], wft[o * 2560 + i], p);
#pragma unroll
    for (int off = 16; off; off >>= 1) p += __shfl_down_sync(0xffffffffu, p, off);
    __shared__ float wsum[4];
    if ((tid & 31) == 0) wsum[tid >> 5] = p;
    __syncthreads();
    if (tid == 0) {
        float tt = wsum[0] + wsum[1] + wsum[2] + wsum[3];
        out[b * 12 + o] = bf[o] + tt / 129.0f;
    }
}

#define SC2_SMEM (49152 * 4)   // 196608 bytes

extern "C" void kernel_launch(void* const* d_in, const int* in_sizes, int n_in,
                              void* d_out, int out_size) {
    const float* x  = (const float*)d_in[0];
    const float* w1 = (const float*)d_in[1];
    const float* w2 = (const float*)d_in[2];
    const float* w3 = (const float*)d_in[3];
    const float* wf = (const float*)d_in[4];
    const float* bf = (const float*)d_in[5];
    float* out = (float*)d_out;

    cudaFuncSetAttribute(k_sconv2, cudaFuncAttributeMaxDynamicSharedMemorySize, SC2_SMEM);

    unsigned char* c1 = nullptr; cudaGetSymbolAddress((void**)&c1, g_cil1);
    unsigned char* n1 = nullptr; cudaGetSymbolAddress((void**)&n1, g_cnt1);
    unsigned char* c2 = nullptr; cudaGetSymbolAddress((void**)&c2, g_cil2);
    unsigned char* n2 = nullptr; cudaGetSymbolAddress((void**)&n2, g_cnt2);
    float* aA = nullptr; cudaGetSymbolAddress((void**)&aA, g_acts);

    k_transpose<<<504, 256>>>(w2, w3, wf);

    // layer 1: conv1 + LIF1 -> list1
    k_conv1_lif<<<320, 256>>>(x, w1);

    // layer 2: segmented systolic conv -> acts; then LIF -> list2
    k_sconv2<<<148, 832, SC2_SMEM>>>(c1, n1, aA);
    k_lif_scan<0><<<320, 256>>>(aA, c2, n2);

    // layer 3: gather conv -> acts; then LIF -> counts
    k_sconv3<<<148, 1024>>>(c2, n2, aA);
    k_lif_scan<1><<<320, 256>>>(aA, nullptr, nullptr);

    // FC head
    k_fc<<<dim3(12, 32), 128>>>(bf, out);
}

// round 8
// speedup vs baseline: 1.4161x; 1.1153x over previous
#include <cuda_runtime.h>

#define B_LEN 32
#define T_IN  128
#define T_LEN 129
#define M_LEN 40
#define NPIX  (B_LEN*T_LEN*M_LEN)            // 165,120
#define NTOT  (NPIX*64)
typedef unsigned long long ull;

// acts: [(b*40+m)*2+half][t][lane]
__device__ float  g_acts[NTOT];
__device__ unsigned char g_cil1[NPIX * 64];
__device__ unsigned char g_cnt1[NPIX * 2];
__device__ unsigned char g_cil2[NPIX * 64];
__device__ unsigned char g_cnt2[NPIX * 2];
__device__ unsigned g_nz[1280];              // layer-3 per-chain nonzero flag
// conv2 paired layout: byte = kw*65536 + ci*1024 + pair*512 + lane*16 + j*4
//   kh = pair*2 + (j>>1), co = (j&1)*32 + lane
__device__ float4 g_wq2[49152 / 4];
// conv3 layout: float idx = tap*4096 + ci*64 + lane*2 + half
__device__ float4 g_wt3[49152 / 4];
__device__ float4 g_wft[30720 / 4];          // [o][m][c]
__device__ float  g_cnt[B_LEN * M_LEN * 64]; // [b][m][c]

__device__ __forceinline__ float lif_tau_div(float num) {
    const float TAUF = 10.0f / 7.0f;
    return __fdiv_rn(num, TAUF);
}
__device__ __forceinline__ void add_f32x2(ull& acc, ull w) {
    asm("add.rn.f32x2 %0, %1, %2;" : "=l"(acc) : "l"(acc), "l"(w));
}

// ---------------- weight transposes + flag reset ----------------
__global__ void k_transpose(const float* __restrict__ w2, const float* __restrict__ w3,
                            const float* __restrict__ wf) {
    int i = blockIdx.x * 256 + threadIdx.x;
    if (i < 1280) g_nz[i] = 0;
    if (i < 49152) {
        int j    = i & 3;
        int lane = (i >> 2) & 31;
        int pair = (i >> 7) & 1;
        int ci   = (i >> 8) & 63;
        int kw   = i >> 14;
        int kh   = pair * 2 + (j >> 1);
        int co   = (j & 1) * 32 + lane;
        ((float*)g_wq2)[i] = w2[co * 768 + ci * 12 + kh * 3 + kw];
    } else if (i < 2 * 49152) {
        int j   = i - 49152;
        int ci  = j & 63;
        int tap = (j >> 6) % 12;
        int co  = j / 768;
        ((float*)g_wt3)[tap * 4096 + ci * 64 + (co & 31) * 2 + (co >> 5)] =
            w3[co * 768 + ci * 12 + tap];
    } else if (i < 2 * 49152 + 30720) {
        int j = i - 2 * 49152;
        int c = j & 63;
        int m = (j >> 6) % 40;
        int o = j / 2560;
        ((float*)g_wft)[j] = wf[o * 2560 + c * 40 + m];
    }
}

// ---------------- conv1 + LIF1 fused: warp per (b,m,half) chain ----------------
__global__ void __launch_bounds__(256) k_conv1_lif(const float* __restrict__ x,
                                                   const float* __restrict__ w1) {
    int w    = (blockIdx.x * 256 + threadIdx.x) >> 5;
    int lane = threadIdx.x & 31;
    unsigned lml = (1u << lane) - 1u;
    int b    = w / 80;
    int r    = w % 80;
    int m    = r >> 1;
    int half = r & 1;
    int co   = half * 32 + lane;

    float wr[12];
#pragma unroll
    for (int k = 0; k < 12; ++k) wr[k] = w1[co * 12 + k];

    const float* xb = x + (size_t)b * T_IN * M_LEN + m;
    bool c0 = (m - 1 >= 0);
    bool c2 = (m + 1 < M_LEN);

    float win[4][3];
#pragma unroll
    for (int i = 0; i < 4; ++i)
#pragma unroll
        for (int j = 0; j < 3; ++j) win[i][j] = 0.0f;
#pragma unroll
    for (int i = 2; i < 4; ++i) {
        int ti = i - 2;
        win[i][0] = c0 ? xb[ti * M_LEN - 1] : 0.0f;
        win[i][1] = xb[ti * M_LEN];
        win[i][2] = c2 ? xb[ti * M_LEN + 1] : 0.0f;
    }

    float v = 0.0f;
    for (int t = 0; t < T_LEN; ++t) {
        float acc = 0.0f;
#pragma unroll
        for (int kh = 0; kh < 4; ++kh)
#pragma unroll
            for (int kw = 0; kw < 3; ++kw)
                acc = fmaf(wr[kh * 3 + kw], win[kh][kw], acc);

        v = v + lif_tau_div(acc - v);
        bool sp = (v >= 1.0f);
        if (sp) v = 0.0f;
        {
            unsigned bal = __ballot_sync(0xffffffffu, sp);
            int pix = (b * T_LEN + t) * M_LEN + m;
            if (sp)
                g_cil1[(size_t)pix * 64 + half * 32 + __popc(bal & lml)] = (unsigned char)lane;
            if (lane == 0)
                g_cnt1[pix * 2 + half] = (unsigned char)__popc(bal);
        }

#pragma unroll
        for (int i = 0; i < 3; ++i)
#pragma unroll
            for (int j = 0; j < 3; ++j) win[i][j] = win[i + 1][j];
        int ti = t + 2;
        bool rv = (ti < T_IN);
        win[3][0] = (rv && c0) ? xb[ti * M_LEN - 1] : 0.0f;
        win[3][1] = rv ? xb[ti * M_LEN] : 0.0f;
        win[3][2] = (rv && c2) ? xb[ti * M_LEN + 1] : 0.0f;
    }
}

// ---------------- conv2: flat-partition systolic ring with list prefetch ----------------
__device__ __forceinline__ void decode_half(const char* wh, unsigned q, int n,
                                            const unsigned* lp, int lpoff,
                                            ull (&acc)[13], int lane) {
    if (!n) return;
#pragma unroll
    for (int k = 0; k < 4; ++k) {
        if (k < n) {
            int ci = __byte_perm(q, 0, 0x4440 + k);
            const char* a = wh + ci * 1024 + lane * 16;
            ulonglong2 v0 = *(const ulonglong2*)a;          // kh0, kh1
            ulonglong2 v1 = *(const ulonglong2*)(a + 512);  // kh2, kh3
            add_f32x2(acc[0], v0.x);
            add_f32x2(acc[4], v0.y);
            add_f32x2(acc[8], v1.x);
            add_f32x2(acc[12], v1.y);
        }
    }
    for (int j = 4; j < n; j += 4) {   // rare tail
        unsigned qq = lp[lpoff + (j >> 2)];
#pragma unroll
        for (int k = 0; k < 4; ++k) {
            if (j + k < n) {
                int ci = __byte_perm(qq, 0, 0x4440 + k);
                const char* a = wh + ci * 1024 + lane * 16;
                ulonglong2 v0 = *(const ulonglong2*)a;
                ulonglong2 v1 = *(const ulonglong2*)(a + 512);
                add_f32x2(acc[0], v0.x);
                add_f32x2(acc[4], v0.y);
                add_f32x2(acc[8], v1.x);
                add_f32x2(acc[12], v1.y);
            }
        }
    }
}

#define CHUNK 47   // outputs per warp: 148*24*47 >= 165120

__global__ void __launch_bounds__(768, 1) k_sconv2(const unsigned char* __restrict__ cil,
                                                   const unsigned char* __restrict__ cntb,
                                                   float* __restrict__ acts) {
    extern __shared__ char wsm[];
    {
        float4* d = (float4*)wsm;
        for (int i = threadIdx.x; i < 12288; i += 768) d[i] = g_wq2[i];
    }
    __syncthreads();

    int lane = threadIdx.x & 31;
    int item = blockIdx.x * 24 + (threadIdx.x >> 5);
    int out0 = item * CHUNK;
    if (out0 >= 1280 * 129) return;
    int nout = min(CHUNK, 1280 * 129 - out0);

    while (nout > 0) {
        int chain = out0 / 129;
        int t0 = out0 - chain * 129;
        int len = min(nout, 129 - t0);
        int t1 = t0 + len;
        int b = chain / 40;
        int m = chain - b * 40;
        int rowb = b * 129 * 40;

        int  kwoff[3];
        bool kwok[3];
#pragma unroll
        for (int kw = 0; kw < 3; ++kw) {
            int mi = m - 3 + 3 * kw;
            kwok[kw]  = ((unsigned)mi < 40u);
            kwoff[kw] = mi;
        }

        ull acc[13];
#pragma unroll
        for (int d = 0; d < 13; ++d) acc[d] = 0ull;

        unsigned cc[3], q0[3], q1[3];
        unsigned ccn[3], q0n[3], q1n[3];

#define LOADROW(TI, C, A0, A1)                                                     \
        {                                                                          \
            int _ti = (TI);                                                        \
            _Pragma("unroll")                                                      \
            for (int kw = 0; kw < 3; ++kw) {                                       \
                bool _v = ((unsigned)_ti < 129u) & kwok[kw];                       \
                int _ip = _v ? (rowb + _ti * 40 + kwoff[kw]) : 0;                  \
                C[kw] = _v ? (unsigned)*(const unsigned short*)(cntb + _ip * 2) : 0u; \
                const unsigned* _lp = (const unsigned*)(cil + (size_t)_ip * 64);   \
                A0[kw] = _lp[0];                                                   \
                A1[kw] = _lp[8];                                                   \
            }                                                                      \
        }

        LOADROW(t0 - 6, cc, q0, q1)
        LOADROW(t0 - 5, ccn, q0n, q1n)

        for (int ti = t0 - 6; ti <= t1 + 5; ++ti) {
            if ((unsigned)ti < 129u) {
#pragma unroll
                for (int kw = 0; kw < 3; ++kw) {
                    unsigned c = cc[kw];
                    if (!c) continue;
                    int inpix = rowb + ti * 40 + kwoff[kw];
                    const unsigned* lp = (const unsigned*)(cil + (size_t)inpix * 64);
                    const char* wkw = wsm + kw * 65536;
                    decode_half(wkw,         q0[kw], (int)(c & 255), lp, 0, acc, lane);
                    decode_half(wkw + 32768, q1[kw], (int)(c >> 8),  lp, 8, acc, lane);
                }
            }
            int t = ti - 6;
            if (t >= t0) {
                union { ull u; float2 f; } r;
                r.u = acc[12];
                size_t row = ((size_t)chain * 2) * 129 + t;
                acts[row * 32 + lane]         = r.f.x;
                acts[(row + 129) * 32 + lane] = r.f.y;
            }
#pragma unroll
            for (int d = 12; d >= 1; --d) acc[d] = acc[d - 1];
            acc[0] = 0ull;
#pragma unroll
            for (int kw = 0; kw < 3; ++kw) {
                cc[kw] = ccn[kw];
                q0[kw] = q0n[kw];
                q1[kw] = q1n[kw];
            }
            LOADROW(ti + 2, ccn, q0n, q1n)
        }
        out0 += len;
        nout -= len;
    }
#undef LOADROW
}

// ---------------- LIF scan: warp per (b,m,half) ----------------
template<int MODE>
__global__ void __launch_bounds__(256) k_lif_scan(const float* __restrict__ acts,
                                                  unsigned char* __restrict__ cil,
                                                  unsigned char* __restrict__ cntb) {
    int w    = (blockIdx.x * 256 + threadIdx.x) >> 5;
    int lane = threadIdx.x & 31;
    unsigned lml = (1u << lane) - 1u;
    int b    = w / 80;
    int r    = w % 80;
    int m    = r >> 1;
    int half = r & 1;

    if (MODE == 1) {   // layer-3: skip chains with all-zero acts (v stays exactly 0)
        if (g_nz[b * 40 + m] == 0) {
            g_cnt[b * 2560 + m * 64 + half * 32 + lane] = 0.0f;
            return;
        }
    }

    const float* p = acts + ((size_t)((b * M_LEN + m) * 2 + half) * T_LEN) * 32 + lane;

    float v = 0.0f, scnt = 0.0f;
    float buf[8];
#pragma unroll
    for (int i = 0; i < 8; ++i) buf[i] = p[i * 32];

    for (int t8 = 0; t8 < 128; t8 += 8) {
#pragma unroll
        for (int k = 0; k < 8; ++k) {
            int t = t8 + k;
            float a = buf[k];
            int tn = t + 8;
            if (tn < T_LEN) buf[k] = p[tn * 32];
            v = v + lif_tau_div(a - v);
            bool sp = (v >= 1.0f);
            if (sp) v = 0.0f;
            if (MODE == 0) {
                unsigned bal = __ballot_sync(0xffffffffu, sp);
                int pix = (b * T_LEN + t) * M_LEN + m;
                if (sp) cil[(size_t)pix * 64 + half * 32 + __popc(bal & lml)] = (unsigned char)lane;
                if (lane == 0) cntb[pix * 2 + half] = (unsigned char)__popc(bal);
            } else {
                scnt += sp ? 1.0f : 0.0f;
            }
        }
    }
    {
        float a = buf[0];
        v = v + lif_tau_div(a - v);
        bool sp = (v >= 1.0f);
        if (sp) v = 0.0f;
        if (MODE == 0) {
            unsigned bal = __ballot_sync(0xffffffffu, sp);
            int pix = (b * T_LEN + 128) * M_LEN + m;
            if (sp) cil[(size_t)pix * 64 + half * 32 + __popc(bal & lml)] = (unsigned char)lane;
            if (lane == 0) cntb[pix * 2 + half] = (unsigned char)__popc(bal);
        } else {
            scnt += sp ? 1.0f : 0.0f;
        }
    }
    if (MODE == 1)
        g_cnt[b * 2560 + m * 64 + half * 32 + lane] = scnt;
}

// ---------------- conv3: warp-per-pixel gather + nonzero flagging ----------------
__global__ void __launch_bounds__(1024) k_sconv3(const unsigned char* __restrict__ cil,
                                                 const unsigned char* __restrict__ cntb,
                                                 float* __restrict__ acts) {
    const ull* wt = (const ull*)g_wt3;
    int lane = threadIdx.x & 31;
    int wid  = (blockIdx.x * 1024 + threadIdx.x) >> 5;
    int nw   = gridDim.x * 32;

    for (int pix = wid; pix < NPIX; pix += nw) {
        int b = pix / (T_LEN * M_LEN);
        int r = pix % (T_LEN * M_LEN);
        int t = r / M_LEN;
        int m = r % M_LEN;

        unsigned cc[12];
        unsigned any = 0;
#pragma unroll
        for (int kh = 0; kh < 4; ++kh)
#pragma unroll
            for (int kw = 0; kw < 3; ++kw) {
                int ti = t - 24 + 16 * kh;
                int mi = m - 9 + 9 * kw;
                unsigned c = 0;
                if ((unsigned)ti < 129u && (unsigned)mi < 40u)
                    c = *(const unsigned short*)(cntb + ((b * 129 + ti) * 40 + mi) * 2);
                cc[kh * 3 + kw] = c;
                any |= c;
            }

        ull acc = 0ull;
        if (any) {
            if (lane == 0) g_nz[b * 40 + m] = 1u;
#pragma unroll
            for (int kh = 0; kh < 4; ++kh)
#pragma unroll
                for (int kw = 0; kw < 3; ++kw) {
                    unsigned c = cc[kh * 3 + kw];
                    if (!c) continue;
                    int ti = t - 24 + 16 * kh;
                    int mi = m - 9 + 9 * kw;
                    int inpix = (b * 129 + ti) * 40 + mi;
                    const unsigned char* l8 = cil + (size_t)inpix * 64;
                    int n0 = c & 255;
                    int n1 = c >> 8;
                    const ull* wtap = wt + (kh * 3 + kw) * 2048 + lane;
                    for (int j = 0; j < n0; ++j)
                        add_f32x2(acc, __ldg(wtap + (int)l8[j] * 32));
                    for (int j = 0; j < n1; ++j)
                        add_f32x2(acc, __ldg(wtap + (32 + (int)l8[32 + j]) * 32));
                }
        }
        union { ull u; float2 f; } cv;
        cv.u = acc;
        size_t row = ((size_t)(b * 40 + m) * 2) * 129 + t;
        acts[row * 32 + lane]         = cv.f.x;
        acts[(row + 129) * 32 + lane] = cv.f.y;
    }
}

// ---------------- FC + mean ----------------
__global__ void k_fc(const float* __restrict__ bf, float* __restrict__ out) {
    int o = blockIdx.x;
    int b = blockIdx.y;
    int tid = threadIdx.x;   // 128
    const float* wft = (const float*)g_wft;
    float p = 0.0f;
    for (int i = tid; i < 2560; i += 128)
        p = fmaf(g_cnt[b * 2560 + i], wft[o * 2560 + i], p);
#pragma unroll
    for (int off = 16; off; off >>= 1) p += __shfl_down_sync(0xffffffffu, p, off);
    __shared__ float wsum[4];
    if ((tid & 31) == 0) wsum[tid >> 5] = p;
    __syncthreads();
    if (tid == 0) {
        float tt = wsum[0] + wsum[1] + wsum[2] + wsum[3];
        out[b * 12 + o] = bf[o] + tt / 129.0f;
    }
}

#define SC2_SMEM (49152 * 4)   // 196608 bytes

extern "C" void kernel_launch(void* const* d_in, const int* in_sizes, int n_in,
                              void* d_out, int out_size) {
    const float* x  = (const float*)d_in[0];
    const float* w1 = (const float*)d_in[1];
    const float* w2 = (const float*)d_in[2];
    const float* w3 = (const float*)d_in[3];
    const float* wf = (const float*)d_in[4];
    const float* bf = (const float*)d_in[5];
    float* out = (float*)d_out;

    cudaFuncSetAttribute(k_sconv2, cudaFuncAttributeMaxDynamicSharedMemorySize, SC2_SMEM);

    unsigned char* c1 = nullptr; cudaGetSymbolAddress((void**)&c1, g_cil1);
    unsigned char* n1 = nullptr; cudaGetSymbolAddress((void**)&n1, g_cnt1);
    unsigned char* c2 = nullptr; cudaGetSymbolAddress((void**)&c2, g_cil2);
    unsigned char* n2 = nullptr; cudaGetSymbolAddress((void**)&n2, g_cnt2);
    float* aA = nullptr; cudaGetSymbolAddress((void**)&aA, g_acts);

    k_transpose<<<504, 256>>>(w2, w3, wf);

    // layer 1: conv1 + LIF1 -> list1
    k_conv1_lif<<<320, 256>>>(x, w1);

    // layer 2: flat systolic conv (prefetched lists) -> acts; LIF -> list2
    k_sconv2<<<148, 768, SC2_SMEM>>>(c1, n1, aA);
    k_lif_scan<0><<<320, 256>>>(aA, c2, n2);

    // layer 3: gather conv -> acts (+nz flags); LIF -> counts (skip empty chains)
    k_sconv3<<<148, 1024>>>(c2, n2, aA);
    k_lif_scan<1><<<320, 256>>>(aA, nullptr, nullptr);

    // FC head
    k_fc<<<dim3(12, 32), 128>>>(bf, out);
}

// round 9
// speedup vs baseline: 1.4235x; 1.0052x over previous
#include <cuda_runtime.h>

#define B_LEN 32
#define T_IN  128
#define T_LEN 129
#define M_LEN 40
#define NPIX  (B_LEN*T_LEN*M_LEN)            // 165,120
#define NTOT  (NPIX*64)
typedef unsigned long long ull;

// acts: [(b*40+m)*2+half][t][lane]
__device__ float  g_acts[NTOT];
__device__ unsigned char g_cil1[NPIX * 64];
__device__ unsigned char g_cnt1[NPIX * 2];
__device__ unsigned char g_cil2[NPIX * 64];
__device__ unsigned char g_cnt2[NPIX * 2];
__device__ unsigned g_nz[1280];              // layer-3 per-chain nonzero flag
// conv2/conv3 weights, same layout: float idx = tap*4096 + ci*64 + lane*2 + half
//   (co = half*32 + lane); per (tap,ci): 256B contiguous, LDS.64 per lane at lane*8
__device__ float4 g_wt2[49152 / 4];
__device__ float4 g_wt3[49152 / 4];
__device__ float4 g_wft[30720 / 4];          // [o][m][c]
__device__ float  g_cnt[B_LEN * M_LEN * 64]; // [b][m][c]

__device__ __forceinline__ float lif_tau_div(float num) {
    const float TAUF = 10.0f / 7.0f;
    return __fdiv_rn(num, TAUF);
}
__device__ __forceinline__ void add_f32x2(ull& acc, ull w) {
    asm("add.rn.f32x2 %0, %1, %2;" : "=l"(acc) : "l"(acc), "l"(w));
}

// ---------------- weight transposes + flag reset ----------------
__global__ void k_transpose(const float* __restrict__ w2, const float* __restrict__ w3,
                            const float* __restrict__ wf) {
    int i = blockIdx.x * 256 + threadIdx.x;
    if (i < 1280) g_nz[i] = 0;
    if (i < 2 * 49152) {
        int which = i >= 49152;
        int j  = i - which * 49152;
        int ci  = j & 63;
        int tap = (j >> 6) % 12;
        int co  = j / 768;
        const float* w = which ? w3 : w2;
        float* wt = which ? (float*)g_wt3 : (float*)g_wt2;
        wt[tap * 4096 + ci * 64 + (co & 31) * 2 + (co >> 5)] = w[co * 768 + ci * 12 + tap];
    } else if (i < 2 * 49152 + 30720) {
        int j = i - 2 * 49152;
        int c = j & 63;
        int m = (j >> 6) % 40;
        int o = j / 2560;
        ((float*)g_wft)[j] = wf[o * 2560 + c * 40 + m];
    }
}

// ---------------- conv1 + LIF1 fused: warp per (b,m,half) chain ----------------
__global__ void __launch_bounds__(256) k_conv1_lif(const float* __restrict__ x,
                                                   const float* __restrict__ w1) {
    int w    = (blockIdx.x * 256 + threadIdx.x) >> 5;
    int lane = threadIdx.x & 31;
    unsigned lml = (1u << lane) - 1u;
    int b    = w / 80;
    int r    = w % 80;
    int m    = r >> 1;
    int half = r & 1;
    int co   = half * 32 + lane;

    float wr[12];
#pragma unroll
    for (int k = 0; k < 12; ++k) wr[k] = w1[co * 12 + k];

    const float* xb = x + (size_t)b * T_IN * M_LEN + m;
    bool c0 = (m - 1 >= 0);
    bool c2 = (m + 1 < M_LEN);

    float win[4][3];
#pragma unroll
    for (int i = 0; i < 4; ++i)
#pragma unroll
        for (int j = 0; j < 3; ++j) win[i][j] = 0.0f;
#pragma unroll
    for (int i = 2; i < 4; ++i) {
        int ti = i - 2;
        win[i][0] = c0 ? xb[ti * M_LEN - 1] : 0.0f;
        win[i][1] = xb[ti * M_LEN];
        win[i][2] = c2 ? xb[ti * M_LEN + 1] : 0.0f;
    }

    float v = 0.0f;
    for (int t = 0; t < T_LEN; ++t) {
        float acc = 0.0f;
#pragma unroll
        for (int kh = 0; kh < 4; ++kh)
#pragma unroll
            for (int kw = 0; kw < 3; ++kw)
                acc = fmaf(wr[kh * 3 + kw], win[kh][kw], acc);

        v = v + lif_tau_div(acc - v);
        bool sp = (v >= 1.0f);
        if (sp) v = 0.0f;
        {
            unsigned bal = __ballot_sync(0xffffffffu, sp);
            int pix = (b * T_LEN + t) * M_LEN + m;
            if (sp)
                g_cil1[(size_t)pix * 64 + half * 32 + __popc(bal & lml)] = (unsigned char)lane;
            if (lane == 0)
                g_cnt1[pix * 2 + half] = (unsigned char)__popc(bal);
        }

#pragma unroll
        for (int i = 0; i < 3; ++i)
#pragma unroll
            for (int j = 0; j < 3; ++j) win[i][j] = win[i + 1][j];
        int ti = t + 2;
        bool rv = (ti < T_IN);
        win[3][0] = (rv && c0) ? xb[ti * M_LEN - 1] : 0.0f;
        win[3][1] = rv ? xb[ti * M_LEN] : 0.0f;
        win[3][2] = (rv && c2) ? xb[ti * M_LEN + 1] : 0.0f;
    }
}

// ---------------- sparse gather conv: warp per output pixel, full MLP ----------------
// Per pixel: batch-load 12 counts, then 24 predicated list first-words, then decode
// from registers (global tail for n>4 per half). Order: tap asc, ci asc, half0->half1.
template<int PADT, int DILT, int PADM, int DILM, int FLAG>
__global__ void __launch_bounds__(768, 1) k_sgather(const unsigned char* __restrict__ cil,
                                                    const unsigned char* __restrict__ cntb,
                                                    const float4* __restrict__ wtg,
                                                    float* __restrict__ acts) {
    extern __shared__ char wsm[];   // [tap][ci][64co] floats, 196608 B
    {
        float4* d = (float4*)wsm;
        for (int i = threadIdx.x; i < 12288; i += 768) d[i] = wtg[i];
    }
    __syncthreads();

    int lane = threadIdx.x & 31;
    int wid  = (blockIdx.x * 768 + threadIdx.x) >> 5;
    int nw   = gridDim.x * 24;
    const char* wlane = wsm + lane * 8;

    for (int pix = wid; pix < NPIX; pix += nw) {
        int b = pix / (T_LEN * M_LEN);
        int r = pix % (T_LEN * M_LEN);
        int t = r / M_LEN;
        int m = r % M_LEN;
        int rowb = b * T_LEN * M_LEN;

        // stage 1: all 12 counts (MLP=12)
        unsigned cc[12];
        unsigned any = 0;
#pragma unroll
        for (int kh = 0; kh < 4; ++kh)
#pragma unroll
            for (int kw = 0; kw < 3; ++kw) {
                int ti = t - PADT + DILT * kh;
                int mi = m - PADM + DILM * kw;
                bool v = ((unsigned)ti < (unsigned)T_LEN) & ((unsigned)mi < (unsigned)M_LEN);
                int ip = v ? (rowb + ti * M_LEN + mi) : 0;
                unsigned c = v ? (unsigned)*(const unsigned short*)(cntb + ip * 2) : 0u;
                cc[kh * 3 + kw] = c;
                any |= c;
            }

        ull acc = 0ull;
        if (any) {
            if (FLAG && lane == 0) g_nz[b * M_LEN + m] = 1u;
            // stage 2: predicated list first-words (MLP up to 24)
            unsigned wA[12], wB[12];
#pragma unroll
            for (int kh = 0; kh < 4; ++kh)
#pragma unroll
                for (int kw = 0; kw < 3; ++kw) {
                    int tap = kh * 3 + kw;
                    int ti = t - PADT + DILT * kh;
                    int mi = m - PADM + DILM * kw;
                    int ip = rowb + ti * M_LEN + mi;   // valid whenever cc!=0
                    const unsigned* lp = (const unsigned*)(cil + (size_t)ip * 64);
                    unsigned c = cc[tap];
                    wA[tap] = (c & 255) ? lp[0] : 0u;
                    wB[tap] = (c >> 8)  ? lp[8] : 0u;
                }
            // stage 3: decode from registers
#pragma unroll
            for (int kh = 0; kh < 4; ++kh)
#pragma unroll
                for (int kw = 0; kw < 3; ++kw) {
                    int tap = kh * 3 + kw;
                    unsigned c = cc[tap];
                    if (!c) continue;
                    int n0 = (int)(c & 255);
                    int n1 = (int)(c >> 8);
                    const char* wtap = wlane + tap * 16384;
                    // half0 (ci 0..31)
                    {
                        unsigned q = wA[tap];
#pragma unroll
                        for (int k = 0; k < 4; ++k)
                            if (k < n0) {
                                int ci = __byte_perm(q, 0, 0x4440 + k);
                                add_f32x2(acc, *(const ull*)(wtap + ci * 256));
                            }
                        if (n0 > 4) {
                            int ti = t - PADT + DILT * kh;
                            int mi = m - PADM + DILM * kw;
                            const unsigned* lp = (const unsigned*)
                                (cil + (size_t)(rowb + ti * M_LEN + mi) * 64);
                            for (int j = 4; j < n0; j += 4) {
                                unsigned qq = lp[j >> 2];
#pragma unroll
                                for (int k = 0; k < 4; ++k)
                                    if (j + k < n0) {
                                        int ci = __byte_perm(qq, 0, 0x4440 + k);
                                        add_f32x2(acc, *(const ull*)(wtap + ci * 256));
                                    }
                            }
                        }
                    }
                    // half1 (ci 32..63)
                    {
                        const char* wtap1 = wtap + 32 * 256;
                        unsigned q = wB[tap];
#pragma unroll
                        for (int k = 0; k < 4; ++k)
                            if (k < n1) {
                                int ci = __byte_perm(q, 0, 0x4440 + k);
                                add_f32x2(acc, *(const ull*)(wtap1 + ci * 256));
                            }
                        if (n1 > 4) {
                            int ti = t - PADT + DILT * kh;
                            int mi = m - PADM + DILM * kw;
                            const unsigned* lp = (const unsigned*)
                                (cil + (size_t)(rowb + ti * M_LEN + mi) * 64);
                            for (int j = 4; j < n1; j += 4) {
                                unsigned qq = lp[8 + (j >> 2)];
#pragma unroll
                                for (int k = 0; k < 4; ++k)
                                    if (j + k < n1) {
                                        int ci = __byte_perm(qq, 0, 0x4440 + k);
                                        add_f32x2(acc, *(const ull*)(wtap1 + ci * 256));
                                    }
                            }
                        }
                    }
                }
        }
        union { ull u; float2 f; } cv;
        cv.u = acc;
        size_t row = ((size_t)(b * M_LEN + m) * 2) * T_LEN + t;
        acts[row * 32 + lane]           = cv.f.x;
        acts[(row + T_LEN) * 32 + lane] = cv.f.y;
    }
}

// ---------------- LIF scan: warp per (b,m,half), 16-deep prefetch ----------------
template<int MODE>
__global__ void __launch_bounds__(256) k_lif_scan(const float* __restrict__ acts,
                                                  unsigned char* __restrict__ cil,
                                                  unsigned char* __restrict__ cntb) {
    int w    = (blockIdx.x * 256 + threadIdx.x) >> 5;
    int lane = threadIdx.x & 31;
    unsigned lml = (1u << lane) - 1u;
    int b    = w / 80;
    int r    = w % 80;
    int m    = r >> 1;
    int half = r & 1;

    if (MODE == 1) {   // layer-3: skip all-zero chains (v stays exactly 0)
        if (g_nz[b * 40 + m] == 0) {
            g_cnt[b * 2560 + m * 64 + half * 32 + lane] = 0.0f;
            return;
        }
    }

    const float* p = acts + ((size_t)((b * M_LEN + m) * 2 + half) * T_LEN) * 32 + lane;

    float v = 0.0f, scnt = 0.0f;
    float buf[16];
#pragma unroll
    for (int i = 0; i < 16; ++i) buf[i] = p[i * 32];

    for (int t16 = 0; t16 < 128; t16 += 16) {
#pragma unroll
        for (int k = 0; k < 16; ++k) {
            int t = t16 + k;
            float a = buf[k];
            int tn = t + 16;
            if (tn < T_LEN) buf[k] = p[tn * 32];
            v = v + lif_tau_div(a - v);
            bool sp = (v >= 1.0f);
            if (sp) v = 0.0f;
            if (MODE == 0) {
                unsigned bal = __ballot_sync(0xffffffffu, sp);
                int pix = (b * T_LEN + t) * M_LEN + m;
                if (sp) cil[(size_t)pix * 64 + half * 32 + __popc(bal & lml)] = (unsigned char)lane;
                if (lane == 0) cntb[pix * 2 + half] = (unsigned char)__popc(bal);
            } else {
                scnt += sp ? 1.0f : 0.0f;
            }
        }
    }
    {
        float a = buf[0];
        v = v + lif_tau_div(a - v);
        bool sp = (v >= 1.0f);
        if (sp) v = 0.0f;
        if (MODE == 0) {
            unsigned bal = __ballot_sync(0xffffffffu, sp);
            int pix = (b * T_LEN + 128) * M_LEN + m;
            if (sp) cil[(size_t)pix * 64 + half * 32 + __popc(bal & lml)] = (unsigned char)lane;
            if (lane == 0) cntb[pix * 2 + half] = (unsigned char)__popc(bal);
        } else {
            scnt += sp ? 1.0f : 0.0f;
        }
    }
    if (MODE == 1)
        g_cnt[b * 2560 + m * 64 + half * 32 + lane] = scnt;
}

// ---------------- FC + mean ----------------
__global__ void k_fc(const float* __restrict__ bf, float* __restrict__ out) {
    int o = blockIdx.x;
    int b = blockIdx.y;
    int tid = threadIdx.x;   // 128
    const float* wft = (const float*)g_wft;
    float p = 0.0f;
    for (int i = tid; i < 2560; i += 128)
        p = fmaf(g_cnt[b * 2560 + i], wft[o * 2560 + i], p);
#pragma unroll
    for (int off = 16; off; off >>= 1) p += __shfl_down_sync(0xffffffffu, p, off);
    __shared__ float wsum[4];
    if ((tid & 31) == 0) wsum[tid >> 5] = p;
    __syncthreads();
    if (tid == 0) {
        float tt = wsum[0] + wsum[1] + wsum[2] + wsum[3];
        out[b * 12 + o] = bf[o] + tt / 129.0f;
    }
}

#define SG_SMEM (49152 * 4)   // 196608 bytes

extern "C" void kernel_launch(void* const* d_in, const int* in_sizes, int n_in,
                              void* d_out, int out_size) {
    const float* x  = (const float*)d_in[0];
    const float* w1 = (const float*)d_in[1];
    const float* w2 = (const float*)d_in[2];
    const float* w3 = (const float*)d_in[3];
    const float* wf = (const float*)d_in[4];
    const float* bf = (const float*)d_in[5];
    float* out = (float*)d_out;

    cudaFuncSetAttribute(k_sgather<6, 4, 3, 3, 0>,
                         cudaFuncAttributeMaxDynamicSharedMemorySize, SG_SMEM);
    cudaFuncSetAttribute(k_sgather<24, 16, 9, 9, 1>,
                         cudaFuncAttributeMaxDynamicSharedMemorySize, SG_SMEM);

    unsigned char* c1 = nullptr; cudaGetSymbolAddress((void**)&c1, g_cil1);
    unsigned char* n1 = nullptr; cudaGetSymbolAddress((void**)&n1, g_cnt1);
    unsigned char* c2 = nullptr; cudaGetSymbolAddress((void**)&c2, g_cil2);
    unsigned char* n2 = nullptr; cudaGetSymbolAddress((void**)&n2, g_cnt2);
    float* aA = nullptr; cudaGetSymbolAddress((void**)&aA, g_acts);
    float4* wt2 = nullptr; cudaGetSymbolAddress((void**)&wt2, g_wt2);
    float4* wt3 = nullptr; cudaGetSymbolAddress((void**)&wt3, g_wt3);

    k_transpose<<<504, 256>>>(w2, w3, wf);

    // layer 1: conv1 + LIF1 -> list1
    k_conv1_lif<<<320, 256>>>(x, w1);

    // layer 2: gather conv (full MLP) -> acts; LIF -> list2
    k_sgather<6, 4, 3, 3, 0><<<148, 768, SG_SMEM>>>(c1, n1, wt2, aA);
    k_lif_scan<0><<<320, 256>>>(aA, c2, n2);

    // layer 3: gather conv -> acts (+nz flags); LIF -> counts (skip empty chains)
    k_sgather<24, 16, 9, 9, 1><<<148, 768, SG_SMEM>>>(c2, n2, wt3, aA);
    k_lif_scan<1><<<320, 256>>>(aA, nullptr, nullptr);

    // FC head
    k_fc<<<dim3(12, 32), 128>>>(bf, out);
}